// round 15
// baseline (speedup 1.0000x reference)
#include <cuda_runtime.h>

#define ND 600
#define NPRO 19081
#define NSE 964
#define EMB 128
#define FEAT 2048
#define NE 1200000
#define NPAIRS 8192
#define NANCH 8192
#define KSPLIT 32
#define MPAD 640
#define DBCAP 48               /* drug-neighbor bucket cap (mean ~1.9, Poisson-safe) */

// phase-1 block-role partition (all 256-thread blocks)
#define EDGE_BLKS 700
#define MLP1_BLKS 320          /* 10 row-tiles(64) x 32 k-splits */
#define INIT_BLKS 128          /* transposes, grid-stride */
#define ANCH_BLKS 32           /* 8192 anchors / 256 */
#define P1_GRID (EDGE_BLKS + MLP1_BLKS + INIT_BLKS + ANCH_BLKS)

// ---------------- scratch (static device globals; zero-initialized at load) -----
__device__ float g_part[KSPLIT * MPAD * EMB];   // mlp1 split-K partials
__device__ float g_xd[ND * EMB];                // relu MLP output == xF[:600]
__device__ float g_aggP[ND * EMB];              // protein-neighbor row sums (atomic)
__device__ float g_U[ND * EMB];                 // x600 @ Wa^T
__device__ float g_V[ND * EMB];                 // x600 @ Wb^T
__device__ int   g_deg[ND];                     // TOTAL degree (drug+protein)
__device__ int   g_dcur[ND];                    // drug-bucket cursor
__device__ int   g_dbkt[ND * DBCAP];            // drug-neighbor buckets
__device__ int4  g_pairs[NANCH];                // pre-decoded (ia, ib, s, 0) per anchor
__device__ float g_W2t[EMB * EMB];              // W2^T        [k][o]
__device__ float g_Wlt[EMB * EMB];              // sageWl[1]^T [k][o]
__device__ float g_Wrt[EMB * EMB];              // sageWr[1]^T [k][o]
__device__ float g_W1pt[2 * EMB * EMB];         // outW1^T     [k(0..255)][o]

// edge handler: count degree; drug src -> bucket; protein src -> atomic row-add
__device__ __forceinline__ void edge_handle(int d, int s, const float* __restrict__ protEmb) {
    atomicAdd(&g_deg[d], 1);
    if (s < ND) {
        int p = atomicAdd(&g_dcur[d], 1);
        g_dbkt[d * DBCAP + p] = s;
    } else {
        const float4* pr = (const float4*)(protEmb + (size_t)(s - ND) * EMB);
        float* dp = g_aggP + d * EMB;
#pragma unroll
        for (int c = 0; c < 32; c++) {
            float4 x = pr[c];
            atomicAdd(dp + 4 * c + 0, x.x);
            atomicAdd(dp + 4 * c + 1, x.y);
            atomicAdd(dp + 4 * c + 2, x.z);
            atomicAdd(dp + 4 * c + 3, x.w);
        }
    }
}

// ================= phase 1: edges(+protein agg) | MLP1 GEMM | transposes | anchors
__global__ void k_phase1(const int* __restrict__ ei,
                         const float* __restrict__ A, const float* __restrict__ W,
                         const float* __restrict__ W2, const float* __restrict__ Wl,
                         const float* __restrict__ Wr, const float* __restrict__ oW1,
                         const int* __restrict__ anch, const int* __restrict__ tpl,
                         const float* __restrict__ protEmb) {
    __shared__ __align__(16) float As[16][64];
    __shared__ __align__(16) float Bs[16][128];
    int b = blockIdx.x;
    int t = threadIdx.x;

    if (b < EDGE_BLKS) {
        const int4* dst4 = (const int4*)(ei + NE);
        int stride = EDGE_BLKS * 256;
        for (int i = b * 256 + t; i < NE / 4; i += stride) {
            int4 d4 = dst4[i];
            int base = i * 4;
            if (d4.x < ND) edge_handle(d4.x, ei[base + 0], protEmb);
            if (d4.y < ND) edge_handle(d4.y, ei[base + 1], protEmb);
            if (d4.z < ND) edge_handle(d4.z, ei[base + 2], protEmb);
            if (d4.w < ND) edge_handle(d4.w, ei[base + 3], protEmb);
        }
        return;
    }
    if (b < EDGE_BLKS + MLP1_BLKS) {
        // 64-row tile x 64-wide K slice, 8x4 micro-tile (FFMA; tf32 was slower)
        int tk = b - EDGE_BLKS;
        int rt = tk % 10, ks = tk / 10;
        int tx = t & 31, ty = t >> 5;
        int rowBase = rt * 64;
        int kbase = ks * 64;
        float acc[8][4];
#pragma unroll
        for (int i = 0; i < 8; i++)
#pragma unroll
            for (int j = 0; j < 4; j++) acc[i][j] = 0.f;

        for (int kk = 0; kk < 4; kk++) {
            {
                int r = t >> 2, c4 = t & 3;
                int row = rowBase + r;
                float4 va = make_float4(0.f, 0.f, 0.f, 0.f);
                if (row < ND) va = *(const float4*)(A + row * FEAT + kbase + kk * 16 + c4 * 4);
                As[c4 * 4 + 0][r] = va.x; As[c4 * 4 + 1][r] = va.y;
                As[c4 * 4 + 2][r] = va.z; As[c4 * 4 + 3][r] = va.w;
            }
#pragma unroll
            for (int q = 0; q < 2; q++) {
                int idx = t + q * 256;
                int wr = idx >> 2, wc = idx & 3;
                float4 vb = *(const float4*)(W + wr * FEAT + kbase + kk * 16 + wc * 4);
                Bs[wc * 4 + 0][wr] = vb.x; Bs[wc * 4 + 1][wr] = vb.y;
                Bs[wc * 4 + 2][wr] = vb.z; Bs[wc * 4 + 3][wr] = vb.w;
            }
            __syncthreads();
#pragma unroll
            for (int k = 0; k < 16; k++) {
                float a[8], bb[4];
                *(float4*)(a)     = *(const float4*)&As[k][ty * 8];
                *(float4*)(a + 4) = *(const float4*)&As[k][ty * 8 + 4];
                *(float4*)(bb)    = *(const float4*)&Bs[k][tx * 4];
#pragma unroll
                for (int i = 0; i < 8; i++)
#pragma unroll
                    for (int j = 0; j < 4; j++) acc[i][j] += a[i] * bb[j];
            }
            __syncthreads();
        }
        float* out = g_part + ks * (MPAD * EMB) + rowBase * EMB;
#pragma unroll
        for (int i = 0; i < 8; i++) {
            float4 v = make_float4(acc[i][0], acc[i][1], acc[i][2], acc[i][3]);
            *(float4*)(out + (ty * 8 + i) * EMB + tx * 4) = v;
        }
        return;
    }
    if (b < EDGE_BLKS + MLP1_BLKS + INIT_BLKS) {
        int base = (b - EDGE_BLKS - MLP1_BLKS) * 256 + t;      // [0, 32768)
        for (int idx = base; idx < 81920; idx += INIT_BLKS * 256) {
            if (idx < 16384) {
                int k = idx >> 7, o = idx & 127;
                g_W2t[idx] = W2[o * 128 + k];
            } else if (idx < 32768) {
                int f = idx - 16384; int k = f >> 7, o = f & 127;
                g_Wlt[f] = Wl[o * 128 + k];
            } else if (idx < 49152) {
                int f = idx - 32768; int k = f >> 7, o = f & 127;
                g_Wrt[f] = Wr[o * 128 + k];
            } else {
                int f = idx - 49152; int k = f >> 7, o = f & 127;   // k in [0,256)
                g_W1pt[f] = oW1[o * 256 + k];
            }
        }
        return;
    }
    // ---- anchor decode role ----
    {
        int i = (b - EDGE_BLKS - MLP1_BLKS - INIT_BLKS) * 256 + t;   // [0, 8192)
        int a = anch[i];
        int p = a / NSE;
        int s = a - p * NSE;
        g_pairs[i] = make_int4(tpl[2 * p], tpl[2 * p + 1], s, 0);
    }
}

// ================= phase 2: split-K reduce + bias + relu + MLP2 (600 x 512) ======
__global__ void k_mlp12(const float* __restrict__ b1, const float* __restrict__ b2) {
    int row = blockIdx.x;
    int t = threadIdx.x;            // 512
    int col = t & 127, q = t >> 7;  // q in [0,4)
    __shared__ float red[512];
    __shared__ float hs[128];
    float s = 0.f;
    const float* p = g_part + row * EMB + col;
#pragma unroll
    for (int i = 0; i < 8; i++) s += p[(q * 8 + i) * (MPAD * EMB)];
    red[t] = s;
    __syncthreads();
    if (t < 128) {
        float h = red[t] + red[t + 128] + red[t + 256] + red[t + 384] + b1[t];
        hs[t] = fmaxf(h, 0.f);
    }
    __syncthreads();
    float a0 = 0.f, a1 = 0.f;
#pragma unroll
    for (int k = 0; k < 32; k += 2) {
        int kk = q * 32 + k;
        a0 += hs[kk] * g_W2t[kk * 128 + col];
        a1 += hs[kk + 1] * g_W2t[(kk + 1) * 128 + col];
    }
    red[t] = a0 + a1;
    __syncthreads();
    if (t < 128) {
        float r = red[t] + red[t + 128] + red[t + 256] + red[t + 384] + b2[t];
        g_xd[row * EMB + t] = fmaxf(r, 0.f);
    }
}

// ================= phase 3: (drug-only) aggregation + SAGE + U/V (600 x 512) =====
__global__ void k_aggsage(const float* __restrict__ bl) {
    int v = blockIdx.x;
    int t = threadIdx.x;            // 512
    int col = t & 127, q = t >> 7;  // q in [0,4)
    __shared__ float redA[512], redB[512];
    __shared__ float s1[128], s2[128], sx[128];
    __shared__ int sidx[DBCAP];
    int deg = g_deg[v];             // total (drug + protein)
    int dn = g_dcur[v];             // drug neighbors only (~2 avg)
    if (t < dn) sidx[t] = g_dbkt[v * DBCAP + t];
    __syncthreads();
    // group 0 carries the precomputed protein sum; all groups add drug rows
    float sum = (q == 0) ? g_aggP[v * EMB + col] : 0.f;
    for (int j = q; j < dn; j += 4) sum += g_xd[sidx[j] * EMB + col];
    redA[t] = sum;
    __syncthreads();
    if (t < 128) {
        float inv = 1.f / fmaxf((float)deg, 1.f);
        s1[t] = (redA[t] + redA[t + 128] + redA[t + 256] + redA[t + 384]) * inv;
        s2[t] = g_xd[v * EMB + t];
    }
    __syncthreads();
    // SAGE GEMV, K split 4 ways
    {
        float a0 = 0.f, a1 = 0.f;
#pragma unroll
        for (int k0 = 0; k0 < 32; k0 += 2) {
            int k = q * 32 + k0;
            a0 += s1[k] * g_Wlt[k * 128 + col] + s2[k] * g_Wrt[k * 128 + col];
            a1 += s1[k + 1] * g_Wlt[(k + 1) * 128 + col] + s2[k + 1] * g_Wrt[(k + 1) * 128 + col];
        }
        redA[t] = a0 + a1;
    }
    __syncthreads();
    if (t < 128)
        sx[t] = fmaxf(redA[t] + redA[t + 128] + redA[t + 256] + redA[t + 384] + bl[t], 0.f);
    __syncthreads();
    // U/V GEMV, K split 4 ways
    {
        float u0 = 0.f, w0 = 0.f;
#pragma unroll
        for (int k0 = 0; k0 < 32; k0++) {
            int k = q * 32 + k0;
            float x = sx[k];
            u0 += x * g_W1pt[k * 128 + col];
            w0 += x * g_W1pt[(128 + k) * 128 + col];
        }
        redA[t] = u0; redB[t] = w0;
    }
    __syncthreads();
    if (t < 128) {
        g_U[v * EMB + t] = redA[t] + redA[t + 128] + redA[t + 256] + redA[t + 384];
        g_V[v * EMB + t] = redB[t] + redB[t + 128] + redB[t + 256] + redB[t + 384];
    }
}

// ================= phase 4: pair MLP + anchor dot (+ scratch reset for replay) ===
__global__ void k_final(const float* __restrict__ ob1, const float* __restrict__ oW2,
                        const float* __restrict__ ob2, float* __restrict__ out) {
    int gid = blockIdx.x * 256 + threadIdx.x;   // 1024 blocks x 256 = 262144
    if (gid < ND) { g_deg[gid] = 0; g_dcur[gid] = 0; }
    if (gid < ND * EMB) g_aggP[gid] = 0.f;      // reset accumulator for next call
    int w = gid >> 5;                           // 0..8191
    int lane = threadIdx.x & 31;
    int4 pr = g_pairs[w];                       // (ia, ib, s, 0) — broadcast load
    float4 u = ((const float4*)g_U)[pr.x * 32 + lane];
    float4 v = ((const float4*)g_V)[pr.y * 32 + lane];
    float4 y = ((const float4*)(oW2 + pr.z * EMB))[lane];
    float4 b = ((const float4*)ob1)[lane];
    float x0 = fmaxf(u.x + v.x + b.x, 0.f);
    float x1 = fmaxf(u.y + v.y + b.y, 0.f);
    float x2 = fmaxf(u.z + v.z + b.z, 0.f);
    float x3 = fmaxf(u.w + v.w + b.w, 0.f);
    float d = x0 * y.x + x1 * y.y + x2 * y.z + x3 * y.w;
#pragma unroll
    for (int off = 16; off; off >>= 1) d += __shfl_xor_sync(0xffffffffu, d, off);
    if (lane == 0) out[w] = fmaxf(d + ob2[pr.z], 0.f);
}

// ---------------- launch ----------------
extern "C" void kernel_launch(void* const* d_in, const int* in_sizes, int n_in,
                              void* d_out, int out_size) {
    const int*   ei      = (const int*)d_in[0];
    const float* drugF   = (const float*)d_in[1];
    const int*   tpl     = (const int*)d_in[2];
    const int*   anch    = (const int*)d_in[3];
    const float* W1      = (const float*)d_in[4];
    const float* b1      = (const float*)d_in[5];
    const float* W2      = (const float*)d_in[6];
    const float* b2      = (const float*)d_in[7];
    const float* protEmb = (const float*)d_in[8];
    const float* sageWl  = (const float*)d_in[9];
    const float* sagebl  = (const float*)d_in[10];
    const float* sageWr  = (const float*)d_in[11];
    const float* outW1   = (const float*)d_in[12];
    const float* outb1   = (const float*)d_in[13];
    const float* outW2   = (const float*)d_in[14];
    const float* outb2   = (const float*)d_in[15];
    float* out = (float*)d_out;

    k_phase1<<<P1_GRID, 256>>>(ei, drugF, W1,
                               W2, sageWl + EMB * EMB, sageWr + EMB * EMB, outW1,
                               anch, tpl, protEmb);
    k_mlp12<<<600, 512>>>(b1, b2);
    k_aggsage<<<600, 512>>>(sagebl + EMB);
    k_final<<<1024, 256>>>(outb1, outW2, outb2, out);
}

// round 16
// speedup vs baseline: 1.0030x; 1.0030x over previous
#include <cuda_runtime.h>

#define ND 600
#define NPRO 19081
#define NSE 964
#define EMB 128
#define FEAT 2048
#define NE 1200000
#define NPAIRS 8192
#define NANCH 8192
#define KSPLIT 32
#define MPAD 640
#define DBCAP 48               /* drug-neighbor bucket cap (mean ~1.9, Poisson-safe) */

// phase-1 block-role partition (all 256-thread blocks)
#define EDGE_BLKS 700
#define MLP1_BLKS 320          /* 10 row-tiles(64) x 32 k-splits */
#define INIT_BLKS 128          /* transposes, grid-stride */
#define ANCH_BLKS 32           /* 8192 anchors / 256 */
#define P1_GRID (EDGE_BLKS + MLP1_BLKS + INIT_BLKS + ANCH_BLKS)

// ---------------- scratch (static device globals; zero-initialized at load) -----
__device__ float g_part[KSPLIT * MPAD * EMB];   // mlp1 split-K partials
__device__ float g_xd[ND * EMB];                // relu MLP output == xF[:600]
__device__ float g_aggP[ND * EMB];              // protein-neighbor row sums (atomic)
__device__ float g_U[ND * EMB];                 // x600 @ Wa^T
__device__ float g_V[ND * EMB];                 // x600 @ Wb^T
__device__ int   g_deg[ND];                     // TOTAL degree (drug+protein)
__device__ int   g_dcur[ND];                    // drug-bucket cursor
__device__ int   g_dbkt[ND * DBCAP];            // drug-neighbor buckets
__device__ int4  g_pairs[NANCH];                // pre-decoded (ia, ib, s, 0) per anchor
__device__ float g_W2t[EMB * EMB];              // W2^T        [k][o]
__device__ float g_Wlt[EMB * EMB];              // sageWl[1]^T [k][o]
__device__ float g_Wrt[EMB * EMB];              // sageWr[1]^T [k][o]
__device__ float g_W1pt[2 * EMB * EMB];         // outW1^T     [k(0..255)][o]

// edge handler: count degree; drug src -> bucket; protein src -> atomic row-add
__device__ __forceinline__ void edge_handle(int d, int s, const float* __restrict__ protEmb) {
    atomicAdd(&g_deg[d], 1);
    if (s < ND) {
        int p = atomicAdd(&g_dcur[d], 1);
        g_dbkt[d * DBCAP + p] = s;
    } else {
        const float4* pr = (const float4*)(protEmb + (size_t)(s - ND) * EMB);
        float* dp = g_aggP + d * EMB;
#pragma unroll
        for (int c = 0; c < 32; c++) {
            float4 x = pr[c];
            atomicAdd(dp + 4 * c + 0, x.x);
            atomicAdd(dp + 4 * c + 1, x.y);
            atomicAdd(dp + 4 * c + 2, x.z);
            atomicAdd(dp + 4 * c + 3, x.w);
        }
    }
}

// ================= phase 1: edges(+protein agg) | MLP1 GEMM | transposes | anchors
__global__ void k_phase1(const int* __restrict__ ei,
                         const float* __restrict__ A, const float* __restrict__ W,
                         const float* __restrict__ W2, const float* __restrict__ Wl,
                         const float* __restrict__ Wr, const float* __restrict__ oW1,
                         const int* __restrict__ anch, const int* __restrict__ tpl,
                         const float* __restrict__ protEmb) {
    __shared__ __align__(16) float As[16][64];
    __shared__ __align__(16) float Bs[16][128];
    int b = blockIdx.x;
    int t = threadIdx.x;

    if (b < EDGE_BLKS) {
        const int4* dst4 = (const int4*)(ei + NE);
        int stride = EDGE_BLKS * 256;
        for (int i = b * 256 + t; i < NE / 4; i += stride) {
            int4 d4 = dst4[i];
            int base = i * 4;
            if (d4.x < ND) edge_handle(d4.x, ei[base + 0], protEmb);
            if (d4.y < ND) edge_handle(d4.y, ei[base + 1], protEmb);
            if (d4.z < ND) edge_handle(d4.z, ei[base + 2], protEmb);
            if (d4.w < ND) edge_handle(d4.w, ei[base + 3], protEmb);
        }
        return;
    }
    if (b < EDGE_BLKS + MLP1_BLKS) {
        // 64-row tile x 64-wide K slice, 8x4 micro-tile (FFMA; tf32 was slower)
        int tk = b - EDGE_BLKS;
        int rt = tk % 10, ks = tk / 10;
        int tx = t & 31, ty = t >> 5;
        int rowBase = rt * 64;
        int kbase = ks * 64;
        float acc[8][4];
#pragma unroll
        for (int i = 0; i < 8; i++)
#pragma unroll
            for (int j = 0; j < 4; j++) acc[i][j] = 0.f;

        for (int kk = 0; kk < 4; kk++) {
            {
                int r = t >> 2, c4 = t & 3;
                int row = rowBase + r;
                float4 va = make_float4(0.f, 0.f, 0.f, 0.f);
                if (row < ND) va = *(const float4*)(A + row * FEAT + kbase + kk * 16 + c4 * 4);
                As[c4 * 4 + 0][r] = va.x; As[c4 * 4 + 1][r] = va.y;
                As[c4 * 4 + 2][r] = va.z; As[c4 * 4 + 3][r] = va.w;
            }
#pragma unroll
            for (int q = 0; q < 2; q++) {
                int idx = t + q * 256;
                int wr = idx >> 2, wc = idx & 3;
                float4 vb = *(const float4*)(W + wr * FEAT + kbase + kk * 16 + wc * 4);
                Bs[wc * 4 + 0][wr] = vb.x; Bs[wc * 4 + 1][wr] = vb.y;
                Bs[wc * 4 + 2][wr] = vb.z; Bs[wc * 4 + 3][wr] = vb.w;
            }
            __syncthreads();
#pragma unroll
            for (int k = 0; k < 16; k++) {
                float a[8], bb[4];
                *(float4*)(a)     = *(const float4*)&As[k][ty * 8];
                *(float4*)(a + 4) = *(const float4*)&As[k][ty * 8 + 4];
                *(float4*)(bb)    = *(const float4*)&Bs[k][tx * 4];
#pragma unroll
                for (int i = 0; i < 8; i++)
#pragma unroll
                    for (int j = 0; j < 4; j++) acc[i][j] += a[i] * bb[j];
            }
            __syncthreads();
        }
        float* out = g_part + ks * (MPAD * EMB) + rowBase * EMB;
#pragma unroll
        for (int i = 0; i < 8; i++) {
            float4 v = make_float4(acc[i][0], acc[i][1], acc[i][2], acc[i][3]);
            *(float4*)(out + (ty * 8 + i) * EMB + tx * 4) = v;
        }
        return;
    }
    if (b < EDGE_BLKS + MLP1_BLKS + INIT_BLKS) {
        int base = (b - EDGE_BLKS - MLP1_BLKS) * 256 + t;      // [0, 32768)
        for (int idx = base; idx < 81920; idx += INIT_BLKS * 256) {
            if (idx < 16384) {
                int k = idx >> 7, o = idx & 127;
                g_W2t[idx] = W2[o * 128 + k];
            } else if (idx < 32768) {
                int f = idx - 16384; int k = f >> 7, o = f & 127;
                g_Wlt[f] = Wl[o * 128 + k];
            } else if (idx < 49152) {
                int f = idx - 32768; int k = f >> 7, o = f & 127;
                g_Wrt[f] = Wr[o * 128 + k];
            } else {
                int f = idx - 49152; int k = f >> 7, o = f & 127;   // k in [0,256)
                g_W1pt[f] = oW1[o * 256 + k];
            }
        }
        return;
    }
    // ---- anchor decode role ----
    {
        int i = (b - EDGE_BLKS - MLP1_BLKS - INIT_BLKS) * 256 + t;   // [0, 8192)
        int a = anch[i];
        int p = a / NSE;
        int s = a - p * NSE;
        g_pairs[i] = make_int4(tpl[2 * p], tpl[2 * p + 1], s, 0);
    }
}

// ================= phase 2: split-K reduce + bias + relu + MLP2 (600 x 512) ======
__global__ void k_mlp12(const float* __restrict__ b1, const float* __restrict__ b2) {
    int row = blockIdx.x;
    int t = threadIdx.x;            // 512
    int col = t & 127, q = t >> 7;  // q in [0,4)
    __shared__ float red[512];
    __shared__ float hs[128];
    float s = 0.f;
    const float* p = g_part + row * EMB + col;
#pragma unroll
    for (int i = 0; i < 8; i++) s += p[(q * 8 + i) * (MPAD * EMB)];
    red[t] = s;
    __syncthreads();
    if (t < 128) {
        float h = red[t] + red[t + 128] + red[t + 256] + red[t + 384] + b1[t];
        hs[t] = fmaxf(h, 0.f);
    }
    __syncthreads();
    float a0 = 0.f, a1 = 0.f;
#pragma unroll
    for (int k = 0; k < 32; k += 2) {
        int kk = q * 32 + k;
        a0 += hs[kk] * g_W2t[kk * 128 + col];
        a1 += hs[kk + 1] * g_W2t[(kk + 1) * 128 + col];
    }
    red[t] = a0 + a1;
    __syncthreads();
    if (t < 128) {
        float r = red[t] + red[t + 128] + red[t + 256] + red[t + 384] + b2[t];
        g_xd[row * EMB + t] = fmaxf(r, 0.f);
    }
}

// ================= phase 3: (drug-only) aggregation + SAGE + U/V (600 x 512) =====
__global__ void k_aggsage(const float* __restrict__ bl) {
    int v = blockIdx.x;
    int t = threadIdx.x;            // 512
    int col = t & 127, q = t >> 7;  // q in [0,4)
    __shared__ float redA[512], redB[512];
    __shared__ float s1[128], s2[128], sx[128];
    __shared__ int sidx[DBCAP];
    int deg = g_deg[v];             // total (drug + protein)
    int dn = g_dcur[v];             // drug neighbors only (~2 avg)
    if (t < dn) sidx[t] = g_dbkt[v * DBCAP + t];
    __syncthreads();
    // group 0 carries the precomputed protein sum; all groups add drug rows
    float sum = (q == 0) ? g_aggP[v * EMB + col] : 0.f;
    for (int j = q; j < dn; j += 4) sum += g_xd[sidx[j] * EMB + col];
    redA[t] = sum;
    __syncthreads();
    if (t < 128) {
        float inv = 1.f / fmaxf((float)deg, 1.f);
        s1[t] = (redA[t] + redA[t + 128] + redA[t + 256] + redA[t + 384]) * inv;
        s2[t] = g_xd[v * EMB + t];
    }
    __syncthreads();
    // SAGE GEMV, K split 4 ways
    {
        float a0 = 0.f, a1 = 0.f;
#pragma unroll
        for (int k0 = 0; k0 < 32; k0 += 2) {
            int k = q * 32 + k0;
            a0 += s1[k] * g_Wlt[k * 128 + col] + s2[k] * g_Wrt[k * 128 + col];
            a1 += s1[k + 1] * g_Wlt[(k + 1) * 128 + col] + s2[k + 1] * g_Wrt[(k + 1) * 128 + col];
        }
        redA[t] = a0 + a1;
    }
    __syncthreads();
    if (t < 128)
        sx[t] = fmaxf(redA[t] + redA[t + 128] + redA[t + 256] + redA[t + 384] + bl[t], 0.f);
    __syncthreads();
    // U/V GEMV, K split 4 ways
    {
        float u0 = 0.f, w0 = 0.f;
#pragma unroll
        for (int k0 = 0; k0 < 32; k0++) {
            int k = q * 32 + k0;
            float x = sx[k];
            u0 += x * g_W1pt[k * 128 + col];
            w0 += x * g_W1pt[(128 + k) * 128 + col];
        }
        redA[t] = u0; redB[t] = w0;
    }
    __syncthreads();
    if (t < 128) {
        g_U[v * EMB + t] = redA[t] + redA[t + 128] + redA[t + 256] + redA[t + 384];
        g_V[v * EMB + t] = redB[t] + redB[t + 128] + redB[t + 256] + redB[t + 384];
    }
}

// ================= phase 4: pair MLP + anchor dot (+ scratch reset for replay) ===
__global__ void k_final(const float* __restrict__ ob1, const float* __restrict__ oW2,
                        const float* __restrict__ ob2, float* __restrict__ out) {
    int gid = blockIdx.x * 256 + threadIdx.x;   // 1024 blocks x 256 = 262144
    if (gid < ND) { g_deg[gid] = 0; g_dcur[gid] = 0; }
    if (gid < ND * EMB) g_aggP[gid] = 0.f;      // reset accumulator for next call
    int w = gid >> 5;                           // 0..8191
    int lane = threadIdx.x & 31;
    int4 pr = g_pairs[w];                       // (ia, ib, s, 0) — broadcast load
    float4 u = ((const float4*)g_U)[pr.x * 32 + lane];
    float4 v = ((const float4*)g_V)[pr.y * 32 + lane];
    float4 y = ((const float4*)(oW2 + pr.z * EMB))[lane];
    float4 b = ((const float4*)ob1)[lane];
    float x0 = fmaxf(u.x + v.x + b.x, 0.f);
    float x1 = fmaxf(u.y + v.y + b.y, 0.f);
    float x2 = fmaxf(u.z + v.z + b.z, 0.f);
    float x3 = fmaxf(u.w + v.w + b.w, 0.f);
    float d = x0 * y.x + x1 * y.y + x2 * y.z + x3 * y.w;
#pragma unroll
    for (int off = 16; off; off >>= 1) d += __shfl_xor_sync(0xffffffffu, d, off);
    if (lane == 0) out[w] = fmaxf(d + ob2[pr.z], 0.f);
}

// ---------------- launch ----------------
extern "C" void kernel_launch(void* const* d_in, const int* in_sizes, int n_in,
                              void* d_out, int out_size) {
    const int*   ei      = (const int*)d_in[0];
    const float* drugF   = (const float*)d_in[1];
    const int*   tpl     = (const int*)d_in[2];
    const int*   anch    = (const int*)d_in[3];
    const float* W1      = (const float*)d_in[4];
    const float* b1      = (const float*)d_in[5];
    const float* W2      = (const float*)d_in[6];
    const float* b2      = (const float*)d_in[7];
    const float* protEmb = (const float*)d_in[8];
    const float* sageWl  = (const float*)d_in[9];
    const float* sagebl  = (const float*)d_in[10];
    const float* sageWr  = (const float*)d_in[11];
    const float* outW1   = (const float*)d_in[12];
    const float* outb1   = (const float*)d_in[13];
    const float* outW2   = (const float*)d_in[14];
    const float* outb2   = (const float*)d_in[15];
    float* out = (float*)d_out;

    k_phase1<<<P1_GRID, 256>>>(ei, drugF, W1,
                               W2, sageWl + EMB * EMB, sageWr + EMB * EMB, outW1,
                               anch, tpl, protEmb);
    k_mlp12<<<600, 512>>>(b1, b2);
    k_aggsage<<<600, 512>>>(sagebl + EMB);
    k_final<<<1024, 256>>>(outb1, outW2, outb2, out);
}

// round 17
// speedup vs baseline: 1.4181x; 1.4138x over previous
#include <cuda_runtime.h>

#define ND 600
#define NPRO 19081
#define NSE 964
#define EMB 128
#define FEAT 2048
#define NE 1200000
#define NPAIRS 8192
#define NANCH 8192
#define KSPLIT 32
#define MPAD 640
#define BCAP 160

// phase-1 block-role partition (all 256-thread blocks)
#define EDGE_BLKS 516
#define MLP1_BLKS 320          /* 10 row-tiles(64) x 32 k-splits */
#define INIT_BLKS 320          /* 81920 transpose elements / 256 */
#define ANCH_BLKS 32           /* 8192 anchors / 256 */
#define P1_GRID (EDGE_BLKS + MLP1_BLKS + INIT_BLKS + ANCH_BLKS)

// ---------------- scratch (static device globals; zero-initialized at load) -----
__device__ float g_part[KSPLIT * MPAD * EMB];   // mlp1 split-K partials
__device__ float g_xd[ND * EMB];                // relu MLP output == xF[:600]
__device__ float g_sP[ND * EMB];                // protein-neighbor row sums
__device__ float g_U[ND * EMB];                 // x600 @ Wa^T
__device__ float g_V[ND * EMB];                 // x600 @ Wb^T
__device__ int   g_deg[ND];                     // degree == bucket cursor (zeroed by k_final)
__device__ int   g_bkt[ND * BCAP];              // per-node src buckets (mixed drug/protein)
__device__ int4  g_pairs[NANCH];                // pre-decoded (ia, ib, s, 0) per anchor
__device__ float g_W2t[EMB * EMB];              // W2^T        [k][o]
__device__ float g_Wlt[EMB * EMB];              // sageWl[1]^T [k][o]
__device__ float g_Wrt[EMB * EMB];              // sageWr[1]^T [k][o]
__device__ float g_W1pt[2 * EMB * EMB];         // outW1^T     [k(0..255)][o]

// ================= phase 1: edges + MLP1 GEMM(8x4) + transposes + anchors ========
__global__ void k_phase1(const int* __restrict__ ei,
                         const float* __restrict__ A, const float* __restrict__ W,
                         const float* __restrict__ W2, const float* __restrict__ Wl,
                         const float* __restrict__ Wr, const float* __restrict__ oW1,
                         const int* __restrict__ anch, const int* __restrict__ tpl) {
    __shared__ __align__(16) float As[16][64];
    __shared__ __align__(16) float Bs[16][128];
    int b = blockIdx.x;
    int t = threadIdx.x;

    if (b < EDGE_BLKS) {
        const int4* dst4 = (const int4*)(ei + NE);
        int stride = EDGE_BLKS * 256;
        for (int i = b * 256 + t; i < NE / 4; i += stride) {
            int4 d4 = dst4[i];
            int base = i * 4;
            if (d4.x < ND) { int p = atomicAdd(&g_deg[d4.x], 1); g_bkt[d4.x * BCAP + p] = ei[base + 0]; }
            if (d4.y < ND) { int p = atomicAdd(&g_deg[d4.y], 1); g_bkt[d4.y * BCAP + p] = ei[base + 1]; }
            if (d4.z < ND) { int p = atomicAdd(&g_deg[d4.z], 1); g_bkt[d4.z * BCAP + p] = ei[base + 2]; }
            if (d4.w < ND) { int p = atomicAdd(&g_deg[d4.w], 1); g_bkt[d4.w * BCAP + p] = ei[base + 3]; }
        }
        return;
    }
    if (b < EDGE_BLKS + MLP1_BLKS) {
        // 64-row tile x 64-wide K slice, 8x4 micro-tile (FFMA; tf32 measured slower)
        int tk = b - EDGE_BLKS;
        int rt = tk % 10, ks = tk / 10;
        int tx = t & 31, ty = t >> 5;
        int rowBase = rt * 64;
        int kbase = ks * 64;
        float acc[8][4];
#pragma unroll
        for (int i = 0; i < 8; i++)
#pragma unroll
            for (int j = 0; j < 4; j++) acc[i][j] = 0.f;

        for (int kk = 0; kk < 4; kk++) {
            {
                int r = t >> 2, c4 = t & 3;
                int row = rowBase + r;
                float4 va = make_float4(0.f, 0.f, 0.f, 0.f);
                if (row < ND) va = *(const float4*)(A + row * FEAT + kbase + kk * 16 + c4 * 4);
                As[c4 * 4 + 0][r] = va.x; As[c4 * 4 + 1][r] = va.y;
                As[c4 * 4 + 2][r] = va.z; As[c4 * 4 + 3][r] = va.w;
            }
#pragma unroll
            for (int q = 0; q < 2; q++) {
                int idx = t + q * 256;
                int wr = idx >> 2, wc = idx & 3;
                float4 vb = *(const float4*)(W + wr * FEAT + kbase + kk * 16 + wc * 4);
                Bs[wc * 4 + 0][wr] = vb.x; Bs[wc * 4 + 1][wr] = vb.y;
                Bs[wc * 4 + 2][wr] = vb.z; Bs[wc * 4 + 3][wr] = vb.w;
            }
            __syncthreads();
#pragma unroll
            for (int k = 0; k < 16; k++) {
                float a[8], bb[4];
                *(float4*)(a)     = *(const float4*)&As[k][ty * 8];
                *(float4*)(a + 4) = *(const float4*)&As[k][ty * 8 + 4];
                *(float4*)(bb)    = *(const float4*)&Bs[k][tx * 4];
#pragma unroll
                for (int i = 0; i < 8; i++)
#pragma unroll
                    for (int j = 0; j < 4; j++) acc[i][j] += a[i] * bb[j];
            }
            __syncthreads();
        }
        float* out = g_part + ks * (MPAD * EMB) + rowBase * EMB;
#pragma unroll
        for (int i = 0; i < 8; i++) {
            float4 v = make_float4(acc[i][0], acc[i][1], acc[i][2], acc[i][3]);
            *(float4*)(out + (ty * 8 + i) * EMB + tx * 4) = v;
        }
        return;
    }
    if (b < EDGE_BLKS + MLP1_BLKS + INIT_BLKS) {
        int idx = (b - EDGE_BLKS - MLP1_BLKS) * 256 + t;       // [0, 81920)
        if (idx < 16384) {
            int k = idx >> 7, o = idx & 127;
            g_W2t[idx] = W2[o * 128 + k];
        } else if (idx < 32768) {
            int f = idx - 16384; int k = f >> 7, o = f & 127;
            g_Wlt[f] = Wl[o * 128 + k];
        } else if (idx < 49152) {
            int f = idx - 32768; int k = f >> 7, o = f & 127;
            g_Wrt[f] = Wr[o * 128 + k];
        } else {
            int f = idx - 49152; int k = f >> 7, o = f & 127;   // k in [0,256)
            g_W1pt[f] = oW1[o * 256 + k];
        }
        return;
    }
    // ---- anchor decode role ----
    {
        int i = (b - EDGE_BLKS - MLP1_BLKS - INIT_BLKS) * 256 + t;   // [0, 8192)
        int a = anch[i];
        int p = a / NSE;
        int s = a - p * NSE;
        g_pairs[i] = make_int4(tpl[2 * p], tpl[2 * p + 1], s, 0);
    }
}

// ================= phase 2: CONCURRENT roles: mlp12 (b<600) | protein gather =====
__global__ void k_phase2(const float* __restrict__ b1, const float* __restrict__ b2,
                         const float* __restrict__ protEmb) {
    int b = blockIdx.x;
    int t = threadIdx.x;            // 512
    int col = t & 127, q = t >> 7;  // q in [0,4)
    __shared__ float red[512];
    __shared__ float hs[128];
    __shared__ int sidx[BCAP];

    if (b < 600) {
        // ---- mlp12 role: split-K reduce + bias + relu + MLP2 ----
        int row = b;
        float s = 0.f;
        const float* p = g_part + row * EMB + col;
#pragma unroll
        for (int i = 0; i < 8; i++) s += p[(q * 8 + i) * (MPAD * EMB)];
        red[t] = s;
        __syncthreads();
        if (t < 128) {
            float h = red[t] + red[t + 128] + red[t + 256] + red[t + 384] + b1[t];
            hs[t] = fmaxf(h, 0.f);
        }
        __syncthreads();
        float a0 = 0.f, a1 = 0.f;
#pragma unroll
        for (int k = 0; k < 32; k += 2) {
            int kk = q * 32 + k;
            a0 += hs[kk] * g_W2t[kk * 128 + col];
            a1 += hs[kk + 1] * g_W2t[(kk + 1) * 128 + col];
        }
        red[t] = a0 + a1;
        __syncthreads();
        if (t < 128) {
            float r = red[t] + red[t + 128] + red[t + 256] + red[t + 384] + b2[t];
            g_xd[row * EMB + t] = fmaxf(r, 0.f);
        }
    } else {
        // ---- protein-gather role: g_sP[v] = sum of protein-neighbor rows ----
        int v = b - 600;
        int deg = g_deg[v];
        if (t < deg) sidx[t] = g_bkt[v * BCAP + t];
        __syncthreads();
        float sum = 0.f;
#pragma unroll 4
        for (int j = q; j < deg; j += 4) {
            int s = sidx[j];
            if (s >= ND) sum += protEmb[(size_t)(s - ND) * EMB + col];
        }
        red[t] = sum;
        __syncthreads();
        if (t < 128)
            g_sP[v * EMB + t] = red[t] + red[t + 128] + red[t + 256] + red[t + 384];
    }
}

// ================= phase 3: drug-row add + mean + SAGE + U/V (600 x 512) =========
__global__ void k_sage(const float* __restrict__ bl) {
    int v = blockIdx.x;
    int t = threadIdx.x;            // 512
    int col = t & 127, q = t >> 7;  // q in [0,4)
    __shared__ float redA[512], redB[512];
    __shared__ float s1[128], s2[128], sx[128];
    __shared__ int sidx[BCAP];
    int deg = g_deg[v];
    if (t < deg) sidx[t] = g_bkt[v * BCAP + t];
    __syncthreads();
    // drug neighbors only (~2 per node); protein sum precomputed in phase 2
    float sum = (q == 0) ? g_sP[v * EMB + col] : 0.f;
#pragma unroll 4
    for (int j = q; j < deg; j += 4) {
        int s = sidx[j];
        if (s < ND) sum += g_xd[s * EMB + col];
    }
    redA[t] = sum;
    __syncthreads();
    if (t < 128) {
        float inv = 1.f / fmaxf((float)deg, 1.f);
        s1[t] = (redA[t] + redA[t + 128] + redA[t + 256] + redA[t + 384]) * inv;
        s2[t] = g_xd[v * EMB + t];
    }
    __syncthreads();
    // SAGE GEMV, K split 4 ways
    {
        float a0 = 0.f, a1 = 0.f;
#pragma unroll
        for (int k0 = 0; k0 < 32; k0 += 2) {
            int k = q * 32 + k0;
            a0 += s1[k] * g_Wlt[k * 128 + col] + s2[k] * g_Wrt[k * 128 + col];
            a1 += s1[k + 1] * g_Wlt[(k + 1) * 128 + col] + s2[k + 1] * g_Wrt[(k + 1) * 128 + col];
        }
        redA[t] = a0 + a1;
    }
    __syncthreads();
    if (t < 128)
        sx[t] = fmaxf(redA[t] + redA[t + 128] + redA[t + 256] + redA[t + 384] + bl[t], 0.f);
    __syncthreads();
    // U/V GEMV, K split 4 ways
    {
        float u0 = 0.f, w0 = 0.f;
#pragma unroll
        for (int k0 = 0; k0 < 32; k0++) {
            int k = q * 32 + k0;
            float x = sx[k];
            u0 += x * g_W1pt[k * 128 + col];
            w0 += x * g_W1pt[(128 + k) * 128 + col];
        }
        redA[t] = u0; redB[t] = w0;
    }
    __syncthreads();
    if (t < 128) {
        g_U[v * EMB + t] = redA[t] + redA[t + 128] + redA[t + 256] + redA[t + 384];
        g_V[v * EMB + t] = redB[t] + redB[t + 128] + redB[t + 256] + redB[t + 384];
    }
}

// ================= phase 4: pair MLP + anchor dot (+ deg reset for replay) =======
__global__ void k_final(const float* __restrict__ ob1, const float* __restrict__ oW2,
                        const float* __restrict__ ob2, float* __restrict__ out) {
    int gid = blockIdx.x * 256 + threadIdx.x;   // 1024 blocks x 256
    if (gid < ND) g_deg[gid] = 0;               // reset cursor for next call/replay
    int w = gid >> 5;                           // 0..8191
    int lane = threadIdx.x & 31;
    int4 pr = g_pairs[w];                       // (ia, ib, s, 0) — broadcast load
    float4 u = ((const float4*)g_U)[pr.x * 32 + lane];
    float4 v = ((const float4*)g_V)[pr.y * 32 + lane];
    float4 y = ((const float4*)(oW2 + pr.z * EMB))[lane];
    float4 b = ((const float4*)ob1)[lane];
    float x0 = fmaxf(u.x + v.x + b.x, 0.f);
    float x1 = fmaxf(u.y + v.y + b.y, 0.f);
    float x2 = fmaxf(u.z + v.z + b.z, 0.f);
    float x3 = fmaxf(u.w + v.w + b.w, 0.f);
    float d = x0 * y.x + x1 * y.y + x2 * y.z + x3 * y.w;
#pragma unroll
    for (int off = 16; off; off >>= 1) d += __shfl_xor_sync(0xffffffffu, d, off);
    if (lane == 0) out[w] = fmaxf(d + ob2[pr.z], 0.f);
}

// ---------------- launch ----------------
extern "C" void kernel_launch(void* const* d_in, const int* in_sizes, int n_in,
                              void* d_out, int out_size) {
    const int*   ei      = (const int*)d_in[0];
    const float* drugF   = (const float*)d_in[1];
    const int*   tpl     = (const int*)d_in[2];
    const int*   anch    = (const int*)d_in[3];
    const float* W1      = (const float*)d_in[4];
    const float* b1      = (const float*)d_in[5];
    const float* W2      = (const float*)d_in[6];
    const float* b2      = (const float*)d_in[7];
    const float* protEmb = (const float*)d_in[8];
    const float* sageWl  = (const float*)d_in[9];
    const float* sagebl  = (const float*)d_in[10];
    const float* sageWr  = (const float*)d_in[11];
    const float* outW1   = (const float*)d_in[12];
    const float* outb1   = (const float*)d_in[13];
    const float* outW2   = (const float*)d_in[14];
    const float* outb2   = (const float*)d_in[15];
    float* out = (float*)d_out;

    k_phase1<<<P1_GRID, 256>>>(ei, drugF, W1,
                               W2, sageWl + EMB * EMB, sageWr + EMB * EMB, outW1,
                               anch, tpl);
    k_phase2<<<1200, 512>>>(b1, b2, protEmb);
    k_sage<<<600, 512>>>(sagebl + EMB);
    k_final<<<1024, 256>>>(outb1, outW2, outb2, out);
}